// round 5
// baseline (speedup 1.0000x reference)
#include <cuda_runtime.h>
#include <stdint.h>

#define BB 4
#define NN 2000
#define CC 80
#define NCLS 81
#define KPRE 2000
#define MAXOUT 100
#define CAP 8192
#define SCAP 4096
#define NHIST 5120
#define HBASE 0x1EA66
#define SCORE_THR 0.05f
#define IOU_THR 0.5f
#define MAX_RATIO 4.135166556742356f

// ---------------- scratch (device globals; self-cleaning, no allocation) -------
__device__ int                g_cnt[BB];          // zeroed by k_mid after read
__device__ int                g_hist[BB][NHIST];  // zeroed by k_mid after read
__device__ unsigned long long g_keys[BB][CAP];    // only [0,cnt) ever read
__device__ unsigned long long g_skeys[BB][SCAP];  // zeroed by k_nms_out after read
__device__ float4             g_box[BB][KPRE];    // fully overwritten each run
__device__ int                g_outidx[BB][MAXOUT]; // only [0,kcnt) read

__device__ __forceinline__ int bucket_of(unsigned bits) {
    int b = (int)(bits >> 13) - HBASE;
    return min(NHIST - 1, max(0, b));
}

// -------- softmax + threshold + warp-aggregated compact + histogram ------------
__global__ void k_softmax(const float* __restrict__ cls) {
    int warp = (blockIdx.x * blockDim.x + threadIdx.x) >> 5;
    int lane = threadIdx.x & 31;
    if (warp >= BB * NN) return;
    int img = warp / NN, p = warp % NN;
    const float* row = cls + ((size_t)img * NN + p) * NCLS;

    float x0 = row[lane];
    float x1 = row[lane + 32];
    float x2 = (lane < NCLS - 64) ? row[lane + 64] : -1e30f;
    float m = fmaxf(fmaxf(x0, x1), x2);
    #pragma unroll
    for (int o = 16; o; o >>= 1) m = fmaxf(m, __shfl_xor_sync(0xffffffffu, m, o));

    float e0 = expf(x0 - m);
    float e1 = expf(x1 - m);
    float e2 = (lane < NCLS - 64) ? expf(x2 - m) : 0.0f;
    float s = e0 + e1 + e2;
    #pragma unroll
    for (int o = 16; o; o >>= 1) s += __shfl_xor_sync(0xffffffffu, s, o);

    float sc0 = __fdiv_rn(e0, s);
    float sc1 = __fdiv_rn(e1, s);
    float sc2 = __fdiv_rn(e2, s);
    bool p0 = sc0 > SCORE_THR;
    bool p1 = sc1 > SCORE_THR;
    bool p2 = (lane < CC - 64) && (sc2 > SCORE_THR);
    unsigned b0 = __ballot_sync(0xffffffffu, p0);
    unsigned b1 = __ballot_sync(0xffffffffu, p1);
    unsigned b2 = __ballot_sync(0xffffffffu, p2);
    int tot = __popc(b0) + __popc(b1) + __popc(b2);
    int base = 0;
    if (lane == 0 && tot) base = atomicAdd(&g_cnt[img], tot);
    base = __shfl_sync(0xffffffffu, base, 0);
    unsigned lm = (1u << lane) - 1u;

    #pragma unroll
    for (int grp = 0; grp < 3; grp++) {
        bool pr = (grp == 0) ? p0 : (grp == 1) ? p1 : p2;
        if (pr) {
            float sc = (grp == 0) ? sc0 : (grp == 1) ? sc1 : sc2;
            int c = lane + grp * 32;
            int rank = ((grp > 0) ? __popc(b0) : 0) + ((grp > 1) ? __popc(b1) : 0) +
                       __popc(((grp == 0) ? b0 : (grp == 1) ? b1 : b2) & lm);
            int pos = base + rank;
            if (pos < CAP) {
                unsigned flat = (unsigned)(p * CC + c);
                unsigned sb = __float_as_uint(sc);
                g_keys[img][pos] =
                    ((unsigned long long)sb << 32) | (unsigned long long)(~flat);
                atomicAdd(&g_hist[img][bucket_of(sb)], 1);
            }
        }
    }
}

// -------- fused: suffix-scan + scatter + per-bucket sort (1 block/img) ---------
#define SCAN_U (NHIST / 1024)   /* 5 */
__global__ void k_mid() {
    __shared__ int s_off[NHIST];
    __shared__ int s_bc[NHIST];
    __shared__ int s_wtot[32];
    int img = blockIdx.x, t = threadIdx.x;  // 1024
    int lane = t & 31, wid = t >> 5;

    // phase 1: read histogram (descending buckets), zero it, suffix scan
    int cnt[SCAN_U];
    int tsum = 0;
    #pragma unroll
    for (int u = 0; u < SCAN_U; u++) {
        int b = NHIST - 1 - (t * SCAN_U + u);
        cnt[u] = g_hist[img][b];
        g_hist[img][b] = 0;
        s_bc[b] = 0;
        tsum += cnt[u];
    }
    int ws = tsum;
    #pragma unroll
    for (int o = 1; o < 32; o <<= 1) {
        int v = __shfl_up_sync(0xffffffffu, ws, o);
        if (lane >= o) ws += v;
    }
    if (lane == 31) s_wtot[wid] = ws;
    __syncthreads();
    if (wid == 0) {
        int v = s_wtot[lane];
        int sv = v;
        #pragma unroll
        for (int o = 1; o < 32; o <<= 1) {
            int x = __shfl_up_sync(0xffffffffu, sv, o);
            if (lane >= o) sv += x;
        }
        s_wtot[lane] = sv - v;
    }
    __syncthreads();
    int base = s_wtot[wid] + (ws - tsum);
    #pragma unroll
    for (int u = 0; u < SCAN_U; u++) {
        int b = NHIST - 1 - (t * SCAN_U + u);
        s_off[b] = base;
        base += cnt[u];
    }
    int total = min(g_cnt[img], CAP);
    __syncthreads();

    // phase 2: scatter keys to final bucket-ordered slots (smem counters)
    for (int e = t; e < total; e += 1024) {
        unsigned long long key = g_keys[img][e];
        int b = bucket_of((unsigned)(key >> 32));
        int o = s_off[b];
        if (o < 2048) {
            int pos = o + atomicAdd(&s_bc[b], 1);
            if (pos < SCAP) g_skeys[img][pos] = key;
        }
    }
    if (t == 0) g_cnt[img] = 0;
    __syncthreads();

    // phase 3: per-bucket insertion sort (descending by full key)
    #pragma unroll
    for (int u = 0; u < SCAN_U; u++) {
        int b = NHIST - 1 - (t * SCAN_U + u);
        int o = s_off[b];
        if (o < 2048) {
            int end = min(o + s_bc[b], SCAP);
            unsigned long long* a = &g_skeys[img][0];
            for (int i = o + 1; i < end; i++) {
                unsigned long long v = a[i];
                int j = i - 1;
                while (j >= o && a[j] < v) { a[j + 1] = a[j]; j--; }
                a[j + 1] = v;
            }
        }
    }
}

// -------- fused decode + on-the-fly greedy NMS + emit (1 block/img, 512 thr) ---
#define NMST 512
__global__ void k_nms_out(const float* __restrict__ reg,
                          const float* __restrict__ props,
                          const int* __restrict__ hw,
                          float* __restrict__ out) {
    __shared__ float4 sbox[2048];    // class-offset boxes (ref fp)
    __shared__ float  sarea[2048];   // areas from offset coords (ref fp)
    __shared__ unsigned sremv[64];   // bit set = suppressed/invalid
    __shared__ int s_cur, s_k;
    int img = blockIdx.x, tid = threadIdx.x;
    int lane = tid & 31, wid = tid >> 5;

    if (tid < 64) sremv[tid] = 0u;
    if (tid == 0) s_k = 0;
    __syncthreads();

    float h = (float)hw[img * 2 + 0];
    float w = (float)hw[img * 2 + 1];
    float maxhw1 = __fadd_rn(fmaxf(h, w), 1.0f);

    // ---- decode phase (no FMA contraction; matches reference fp) ----
    for (int r = tid; r < 2048; r += NMST) {
        unsigned long long key = (r < KPRE) ? g_skeys[img][r] : 0ULL;
        float sc = __uint_as_float((unsigned)(key >> 32));
        bool valid = (r < KPRE) && (sc > SCORE_THR);
        float4 ob = make_float4(0, 0, 0, 0);
        float ar = 0.0f;
        if (valid) {
            int flat = (int)(~(unsigned)key);
            int p = flat / CC, c = flat % CC;
            const float* pb = props + ((size_t)img * NN + p) * 4;
            const float* dd = reg + (((size_t)img * NN + p) * CC + c) * 4;

            float dx = __fmul_rn(dd[0], 0.1f);
            float dy = __fmul_rn(dd[1], 0.1f);
            float dw = fminf(fmaxf(__fmul_rn(dd[2], 0.2f), -MAX_RATIO), MAX_RATIO);
            float dh = fminf(fmaxf(__fmul_rn(dd[3], 0.2f), -MAX_RATIO), MAX_RATIO);

            float px = __fmul_rn(__fadd_rn(pb[0], pb[2]), 0.5f);
            float py = __fmul_rn(__fadd_rn(pb[1], pb[3]), 0.5f);
            float pw = __fsub_rn(pb[2], pb[0]);
            float ph = __fsub_rn(pb[3], pb[1]);

            float gx = __fadd_rn(px, __fmul_rn(pw, dx));
            float gy = __fadd_rn(py, __fmul_rn(ph, dy));
            float gw = __fmul_rn(pw, expf(dw));
            float gh = __fmul_rn(ph, expf(dh));
            float hx = __fmul_rn(gw, 0.5f);
            float hy = __fmul_rn(gh, 0.5f);

            float x1 = fminf(fmaxf(__fsub_rn(gx, hx), 0.0f), w);
            float y1 = fminf(fmaxf(__fsub_rn(gy, hy), 0.0f), h);
            float x2 = fminf(fmaxf(__fadd_rn(gx, hx), 0.0f), w);
            float y2 = fminf(fmaxf(__fadd_rn(gy, hy), 0.0f), h);

            g_box[img][r] = make_float4(x1, y1, x2, y2);
            float off = __fmul_rn((float)c, maxhw1);
            ob = make_float4(__fadd_rn(x1, off), __fadd_rn(y1, off),
                             __fadd_rn(x2, off), __fadd_rn(y2, off));
            ar = __fmul_rn(__fsub_rn(ob.z, ob.x), __fsub_rn(ob.w, ob.y));
        }
        sbox[r] = ob;
        sarea[r] = ar;
        unsigned bal = __ballot_sync(0xffffffffu, !valid);
        if (lane == 0) atomicOr(&sremv[r >> 5], bal);
    }
    __syncthreads();

    // ---- greedy NMS: <= 100 kept iterations ----
    for (int iter = 0; iter < KPRE; iter++) {
        if (wid == 0) {
            unsigned a0 = ~sremv[lane];
            unsigned a1 = ~sremv[32 + lane];
            unsigned f0 = __ballot_sync(0xffffffffu, a0 != 0);
            unsigned f1 = __ballot_sync(0xffffffffu, a1 != 0);
            int idx = -1;
            if (f0) {
                int l = __ffs(f0) - 1;
                unsigned ww = __shfl_sync(0xffffffffu, a0, l);
                idx = (l << 5) + __ffs(ww) - 1;
            } else if (f1) {
                int l = __ffs(f1) - 1;
                unsigned ww = __shfl_sync(0xffffffffu, a1, l);
                idx = ((32 + l) << 5) + __ffs(ww) - 1;
            }
            if (lane == 0) {
                s_cur = idx;
                if (idx >= 0) {
                    sremv[idx >> 5] |= 1u << (idx & 31);
                    g_outidx[img][s_k] = idx;
                    s_k = s_k + 1;
                }
            }
        }
        __syncthreads();
        int i = s_cur;
        if (i < 0) break;
        float4 bi = sbox[i];
        float ai = sarea[i];
        unsigned nib = 0;
        #pragma unroll
        for (int u = 0; u < 4; u++) {
            int j = (tid << 2) + u;
            if (j > i) {
                float4 bj = sbox[j];
                float ltx = fmaxf(bi.x, bj.x), lty = fmaxf(bi.y, bj.y);
                float rbx = fminf(bi.z, bj.z), rby = fminf(bi.w, bj.w);
                float wx = fmaxf(__fsub_rn(rbx, ltx), 0.0f);
                float wy = fmaxf(__fsub_rn(rby, lty), 0.0f);
                float inter = __fmul_rn(wx, wy);
                float den = __fadd_rn(__fsub_rn(__fadd_rn(ai, sarea[j]), inter), 1e-6f);
                if (__fdiv_rn(inter, den) > IOU_THR) nib |= 1u << u;
            }
        }
        if (nib) atomicOr(&sremv[tid >> 3], nib << ((tid & 7) << 2));
        if (s_k >= MAXOUT) break;
        __syncthreads();
    }
    __syncthreads();

    // ---- emit: boxes[B,100,4] | scores[B,100] | labels[B,100] ----
    int kcnt = s_k;
    if (tid < MAXOUT) {
        int k = tid;
        int idx = (k < kcnt) ? g_outidx[img][k] : -1;
        float4 bx = make_float4(0, 0, 0, 0);
        float sc = 0.0f, lb = -1.0f;
        if (idx >= 0) {
            bx = g_box[img][idx];
            unsigned long long key = g_skeys[img][idx];
            sc = __uint_as_float((unsigned)(key >> 32));
            lb = (float)((int)(~(unsigned)key) % CC);
        }
        float* bo = out + (size_t)(img * MAXOUT + k) * 4;
        bo[0] = bx.x; bo[1] = bx.y; bo[2] = bx.z; bo[3] = bx.w;
        out[BB * MAXOUT * 4 + img * MAXOUT + k] = sc;
        out[BB * MAXOUT * 5 + img * MAXOUT + k] = lb;
    }
    __syncthreads();
    // self-clean skeys for next run
    for (int i2 = tid; i2 < SCAP; i2 += NMST) g_skeys[img][i2] = 0ULL;
}

// ---------------- launch (3 kernels) -------------------------------------------
extern "C" void kernel_launch(void* const* d_in, const int* in_sizes, int n_in,
                              void* d_out, int out_size) {
    const float* cls = (const float*)d_in[0];
    const float* reg = (const float*)d_in[1];
    const float* props = (const float*)d_in[2];
    const int* hw = (const int*)d_in[3];
    float* out = (float*)d_out;

    k_softmax<<<(BB * NN * 32 + 255) / 256, 256>>>(cls);
    k_mid<<<BB, 1024>>>();
    k_nms_out<<<BB, NMST>>>(reg, props, hw, out);
}

// round 6
// speedup vs baseline: 2.2813x; 2.2813x over previous
#include <cuda_runtime.h>
#include <stdint.h>

#define BB 4
#define NN 2000
#define CC 80
#define NCLS 81
#define KPRE 2000
#define MAXOUT 100
#define CAP 8192
#define SCAP 4096
#define NHIST 5120
#define HBASE 0x1EA66
#define SCORE_THR 0.05f
#define IOU_THR 0.5f
#define MAX_RATIO 4.135166556742356f

// ---------------- scratch (device globals; self-cleaning, no allocation) -------
__device__ int                g_cnt[BB];          // zeroed by k_mid after read
__device__ int                g_hist[BB][NHIST];  // zeroed by k_mid after read
__device__ unsigned long long g_keys[BB][CAP];    // only [0,cnt) ever read
__device__ unsigned long long g_skeys[BB][SCAP];  // zeroed by k_nms_out after read

__device__ __forceinline__ int bucket_of(unsigned bits) {
    int b = (int)(bits >> 13) - HBASE;
    return min(NHIST - 1, max(0, b));
}

// -------- softmax + threshold + warp-aggregated compact + histogram ------------
__global__ void k_softmax(const float* __restrict__ cls) {
    int warp = (blockIdx.x * blockDim.x + threadIdx.x) >> 5;
    int lane = threadIdx.x & 31;
    if (warp >= BB * NN) return;
    int img = warp / NN, p = warp % NN;
    const float* row = cls + ((size_t)img * NN + p) * NCLS;

    float x0 = row[lane];
    float x1 = row[lane + 32];
    float x2 = (lane < NCLS - 64) ? row[lane + 64] : -1e30f;
    float m = fmaxf(fmaxf(x0, x1), x2);
    #pragma unroll
    for (int o = 16; o; o >>= 1) m = fmaxf(m, __shfl_xor_sync(0xffffffffu, m, o));

    float e0 = expf(x0 - m);
    float e1 = expf(x1 - m);
    float e2 = (lane < NCLS - 64) ? expf(x2 - m) : 0.0f;
    float s = e0 + e1 + e2;
    #pragma unroll
    for (int o = 16; o; o >>= 1) s += __shfl_xor_sync(0xffffffffu, s, o);

    float sc0 = __fdiv_rn(e0, s);
    float sc1 = __fdiv_rn(e1, s);
    float sc2 = __fdiv_rn(e2, s);
    bool p0 = sc0 > SCORE_THR;
    bool p1 = sc1 > SCORE_THR;
    bool p2 = (lane < CC - 64) && (sc2 > SCORE_THR);
    unsigned b0 = __ballot_sync(0xffffffffu, p0);
    unsigned b1 = __ballot_sync(0xffffffffu, p1);
    unsigned b2 = __ballot_sync(0xffffffffu, p2);
    int tot = __popc(b0) + __popc(b1) + __popc(b2);
    int base = 0;
    if (lane == 0 && tot) base = atomicAdd(&g_cnt[img], tot);
    base = __shfl_sync(0xffffffffu, base, 0);
    unsigned lm = (1u << lane) - 1u;

    #pragma unroll
    for (int grp = 0; grp < 3; grp++) {
        bool pr = (grp == 0) ? p0 : (grp == 1) ? p1 : p2;
        if (pr) {
            float sc = (grp == 0) ? sc0 : (grp == 1) ? sc1 : sc2;
            int c = lane + grp * 32;
            int rank = ((grp > 0) ? __popc(b0) : 0) + ((grp > 1) ? __popc(b1) : 0) +
                       __popc(((grp == 0) ? b0 : (grp == 1) ? b1 : b2) & lm);
            int pos = base + rank;
            if (pos < CAP) {
                unsigned flat = (unsigned)(p * CC + c);
                unsigned sb = __float_as_uint(sc);
                g_keys[img][pos] =
                    ((unsigned long long)sb << 32) | (unsigned long long)(~flat);
                atomicAdd(&g_hist[img][bucket_of(sb)], 1);
            }
        }
    }
}

// -------- fused: suffix-scan + scatter + per-bucket sort (1 block/img) ---------
#define SCAN_U (NHIST / 1024)   /* 5 */
__global__ void k_mid() {
    __shared__ int s_off[NHIST];
    __shared__ int s_bc[NHIST];
    __shared__ int s_wtot[32];
    int img = blockIdx.x, t = threadIdx.x;  // 1024
    int lane = t & 31, wid = t >> 5;

    int cnt[SCAN_U];
    int tsum = 0;
    #pragma unroll
    for (int u = 0; u < SCAN_U; u++) {
        int b = NHIST - 1 - (t * SCAN_U + u);
        cnt[u] = g_hist[img][b];
        g_hist[img][b] = 0;
        s_bc[b] = 0;
        tsum += cnt[u];
    }
    int ws = tsum;
    #pragma unroll
    for (int o = 1; o < 32; o <<= 1) {
        int v = __shfl_up_sync(0xffffffffu, ws, o);
        if (lane >= o) ws += v;
    }
    if (lane == 31) s_wtot[wid] = ws;
    __syncthreads();
    if (wid == 0) {
        int v = s_wtot[lane];
        int sv = v;
        #pragma unroll
        for (int o = 1; o < 32; o <<= 1) {
            int x = __shfl_up_sync(0xffffffffu, sv, o);
            if (lane >= o) sv += x;
        }
        s_wtot[lane] = sv - v;
    }
    __syncthreads();
    int base = s_wtot[wid] + (ws - tsum);
    #pragma unroll
    for (int u = 0; u < SCAN_U; u++) {
        int b = NHIST - 1 - (t * SCAN_U + u);
        s_off[b] = base;
        base += cnt[u];
    }
    int total = min(g_cnt[img], CAP);
    __syncthreads();

    for (int e = t; e < total; e += 1024) {
        unsigned long long key = g_keys[img][e];
        int b = bucket_of((unsigned)(key >> 32));
        int o = s_off[b];
        if (o < 2048) {
            int pos = o + atomicAdd(&s_bc[b], 1);
            if (pos < SCAP) g_skeys[img][pos] = key;
        }
    }
    if (t == 0) g_cnt[img] = 0;
    __syncthreads();

    #pragma unroll
    for (int u = 0; u < SCAN_U; u++) {
        int b = NHIST - 1 - (t * SCAN_U + u);
        int o = s_off[b];
        if (o < 2048) {
            int end = min(o + s_bc[b], SCAP);
            unsigned long long* a = &g_skeys[img][0];
            for (int i = o + 1; i < end; i++) {
                unsigned long long v = a[i];
                int j = i - 1;
                while (j >= o && a[j] < v) { a[j + 1] = a[j]; j--; }
                a[j + 1] = v;
            }
        }
    }
}

// -------- fused decode + per-class parallel greedy NMS + emit ------------------
// smem layout (dynamic):
#define SM_OB    0                    // float4[2048]  offset boxes
#define SM_OUT   32768                // float4[2048]  output boxes
#define SM_AR    65536                // float [2048]  offset areas
#define SM_LAB   73728                // u16   [2048]  class (0xFFFF invalid)
#define SM_ORD   77824                // u16   [2048]  class-grouped order
#define SM_CCNT  81920                // int   [32*80] chunk counts/offsets
#define SM_TOT   92160                // int   [80]
#define SM_START 92480                // int   [80]
#define SM_KEPT  92800                // u32   [64]
#define SM_WPRE  93056                // int   [64]
#define SM_KCNT  93312                // int   [1]
#define SMEMSZ   93440

__global__ void k_nms_out(const float* __restrict__ reg,
                          const float* __restrict__ props,
                          const int* __restrict__ hw,
                          float* __restrict__ out) {
    extern __shared__ unsigned char dyn[];
    float4*  s_ob   = (float4*)(dyn + SM_OB);
    float4*  s_out  = (float4*)(dyn + SM_OUT);
    float*   s_ar   = (float*)(dyn + SM_AR);
    unsigned short* s_lab = (unsigned short*)(dyn + SM_LAB);
    unsigned short* s_ord = (unsigned short*)(dyn + SM_ORD);
    int*     s_ccnt = (int*)(dyn + SM_CCNT);
    int*     s_tot  = (int*)(dyn + SM_TOT);
    int*     s_start= (int*)(dyn + SM_START);
    unsigned* s_kept= (unsigned*)(dyn + SM_KEPT);
    int*     s_wpre = (int*)(dyn + SM_WPRE);
    int*     s_kcnt = (int*)(dyn + SM_KCNT);

    int img = blockIdx.x, tid = threadIdx.x;  // 1024
    int lane = tid & 31, wid = tid >> 5;
    unsigned lmlt = (1u << lane) - 1u;

    for (int i = tid; i < 32 * 80; i += 1024) s_ccnt[i] = 0;

    float h = (float)hw[img * 2 + 0];
    float w = (float)hw[img * 2 + 1];
    float maxhw1 = __fadd_rn(fmaxf(h, w), 1.0f);

    // ---- decode (exact reference fp: no FMA contraction) ----
    #pragma unroll
    for (int it = 0; it < 2; it++) {
        int r = tid + it * 1024;
        unsigned long long key = (r < KPRE) ? g_skeys[img][r] : 0ULL;
        float sc = __uint_as_float((unsigned)(key >> 32));
        bool valid = (r < KPRE) && (sc > SCORE_THR);
        float4 ob = make_float4(0, 0, 0, 0), bx = make_float4(0, 0, 0, 0);
        float ar = 0.0f;
        int c = 0;
        if (valid) {
            int flat = (int)(~(unsigned)key);
            int p = flat / CC; c = flat % CC;
            const float* pb = props + ((size_t)img * NN + p) * 4;
            const float* dd = reg + (((size_t)img * NN + p) * CC + c) * 4;

            float dx = __fmul_rn(dd[0], 0.1f);
            float dy = __fmul_rn(dd[1], 0.1f);
            float dw = fminf(fmaxf(__fmul_rn(dd[2], 0.2f), -MAX_RATIO), MAX_RATIO);
            float dh = fminf(fmaxf(__fmul_rn(dd[3], 0.2f), -MAX_RATIO), MAX_RATIO);

            float px = __fmul_rn(__fadd_rn(pb[0], pb[2]), 0.5f);
            float py = __fmul_rn(__fadd_rn(pb[1], pb[3]), 0.5f);
            float pw = __fsub_rn(pb[2], pb[0]);
            float ph = __fsub_rn(pb[3], pb[1]);

            float gx = __fadd_rn(px, __fmul_rn(pw, dx));
            float gy = __fadd_rn(py, __fmul_rn(ph, dy));
            float gw = __fmul_rn(pw, expf(dw));
            float gh = __fmul_rn(ph, expf(dh));
            float hx = __fmul_rn(gw, 0.5f);
            float hy = __fmul_rn(gh, 0.5f);

            float x1 = fminf(fmaxf(__fsub_rn(gx, hx), 0.0f), w);
            float y1 = fminf(fmaxf(__fsub_rn(gy, hy), 0.0f), h);
            float x2 = fminf(fmaxf(__fadd_rn(gx, hx), 0.0f), w);
            float y2 = fminf(fmaxf(__fadd_rn(gy, hy), 0.0f), h);

            bx = make_float4(x1, y1, x2, y2);
            float off = __fmul_rn((float)c, maxhw1);
            ob = make_float4(__fadd_rn(x1, off), __fadd_rn(y1, off),
                             __fadd_rn(x2, off), __fadd_rn(y2, off));
            ar = __fmul_rn(__fsub_rn(ob.z, ob.x), __fsub_rn(ob.w, ob.y));
        }
        s_ob[r] = ob;
        s_out[r] = bx;
        s_ar[r] = ar;
        s_lab[r] = valid ? (unsigned short)c : (unsigned short)0xFFFF;
        unsigned bal = __ballot_sync(0xffffffffu, valid);
        if (lane == 0) s_kept[r >> 5] = bal;
    }
    __syncthreads();

    // ---- pass 1: per-warp-chunk class counts (chunk = 64 candidates/warp) ----
    #pragma unroll
    for (int half = 0; half < 2; half++) {
        int r = wid * 64 + half * 32 + lane;
        int lab = s_lab[r];
        if (lab != 0xFFFF) atomicAdd(&s_ccnt[wid * 80 + lab], 1);
    }
    __syncthreads();

    // ---- pass 2: chunk-exclusive offsets per class + class totals ----
    if (tid < 80) {
        int acc = 0;
        for (int w2 = 0; w2 < 32; w2++) {
            int v = s_ccnt[w2 * 80 + tid];
            s_ccnt[w2 * 80 + tid] = acc;
            acc += v;
        }
        s_tot[tid] = acc;
    }
    __syncthreads();
    if (tid == 0) {
        int a = 0;
        for (int c2 = 0; c2 < 80; c2++) { s_start[c2] = a; a += s_tot[c2]; }
    }
    __syncthreads();

    // ---- pass 3: stable scatter into class groups ----
    #pragma unroll
    for (int half = 0; half < 2; half++) {
        int r = wid * 64 + half * 32 + lane;
        int lab = s_lab[r];
        bool valid = lab != 0xFFFF;
        unsigned key = valid ? (unsigned)lab : (0x100u + lane);
        unsigned mk = __match_any_sync(0xffffffffu, key);
        if (valid) {
            int rank = __popc(mk & lmlt);
            int pos = s_start[lab] + s_ccnt[wid * 80 + lab] + rank;
            s_ord[pos] = (unsigned short)r;
        }
        __syncwarp();
        if (valid && (mk & lmlt) == 0u) s_ccnt[wid * 80 + lab] += __popc(mk);
        __syncwarp();
    }
    __syncthreads();

    // ---- per-class greedy NMS (warp per class; classes are independent) ----
    for (int c2 = wid; c2 < 80; c2 += 32) {
        int st = s_start[c2], en = st + s_tot[c2];
        for (int i = st; i < en - 1; i++) {
            int ri = s_ord[i];
            unsigned aw = s_kept[ri >> 5];
            if (aw & (1u << (ri & 31))) {
                float4 bi = s_ob[ri];
                float ai = s_ar[ri];
                for (int j = i + 1 + lane; j < en; j += 32) {
                    int rj = s_ord[j];
                    if (s_kept[rj >> 5] & (1u << (rj & 31))) {
                        float4 bj = s_ob[rj];
                        float ltx = fmaxf(bi.x, bj.x), lty = fmaxf(bi.y, bj.y);
                        float rbx = fminf(bi.z, bj.z), rby = fminf(bi.w, bj.w);
                        float wx = fmaxf(__fsub_rn(rbx, ltx), 0.0f);
                        float wy = fmaxf(__fsub_rn(rby, lty), 0.0f);
                        float inter = __fmul_rn(wx, wy);
                        float den = __fadd_rn(
                            __fsub_rn(__fadd_rn(ai, s_ar[rj]), inter), 1e-6f);
                        if (__fdiv_rn(inter, den) > IOU_THR)
                            atomicAnd(&s_kept[rj >> 5], ~(1u << (rj & 31)));
                    }
                }
            }
            __syncwarp();
        }
    }
    __syncthreads();

    // ---- kept-bitmap exclusive prefix popcount (warp 0) ----
    if (wid == 0) {
        int v0 = __popc(s_kept[lane]);
        int v1 = __popc(s_kept[32 + lane]);
        int s0 = v0, s1 = v1;
        #pragma unroll
        for (int o = 1; o < 32; o <<= 1) {
            int x = __shfl_up_sync(0xffffffffu, s0, o);
            if (lane >= o) s0 += x;
            int y = __shfl_up_sync(0xffffffffu, s1, o);
            if (lane >= o) s1 += y;
        }
        int t0 = __shfl_sync(0xffffffffu, s0, 31);
        s_wpre[lane] = s0 - v0;
        s_wpre[32 + lane] = t0 + s1 - v1;
        if (lane == 31) *s_kcnt = t0 + s1;
    }
    __syncthreads();

    // ---- emit: boxes[B,100,4] | scores[B,100] | labels[B,100] ----
    int kc = *s_kcnt;
    if (tid < MAXOUT && tid >= kc) {
        float* bo = out + (size_t)(img * MAXOUT + tid) * 4;
        bo[0] = 0.0f; bo[1] = 0.0f; bo[2] = 0.0f; bo[3] = 0.0f;
        out[BB * MAXOUT * 4 + img * MAXOUT + tid] = 0.0f;
        out[BB * MAXOUT * 5 + img * MAXOUT + tid] = -1.0f;
    }
    #pragma unroll
    for (int it = 0; it < 2; it++) {
        int r = tid + it * 1024;
        unsigned wrd = s_kept[r >> 5];
        if (wrd & (1u << (r & 31))) {
            int rank = s_wpre[r >> 5] + __popc(wrd & ((1u << (r & 31)) - 1u));
            if (rank < MAXOUT) {
                float4 bx = s_out[r];
                unsigned long long key = g_skeys[img][r];
                float sc = __uint_as_float((unsigned)(key >> 32));
                float lb = (float)((int)(~(unsigned)key) % CC);
                float* bo = out + (size_t)(img * MAXOUT + rank) * 4;
                bo[0] = bx.x; bo[1] = bx.y; bo[2] = bx.z; bo[3] = bx.w;
                out[BB * MAXOUT * 4 + img * MAXOUT + rank] = sc;
                out[BB * MAXOUT * 5 + img * MAXOUT + rank] = lb;
            }
        }
    }
    __syncthreads();
    for (int i = tid; i < SCAP; i += 1024) g_skeys[img][i] = 0ULL;
}

// ---------------- launch (3 kernels) -------------------------------------------
extern "C" void kernel_launch(void* const* d_in, const int* in_sizes, int n_in,
                              void* d_out, int out_size) {
    const float* cls = (const float*)d_in[0];
    const float* reg = (const float*)d_in[1];
    const float* props = (const float*)d_in[2];
    const int* hw = (const int*)d_in[3];
    float* out = (float*)d_out;

    cudaFuncSetAttribute(k_nms_out, cudaFuncAttributeMaxDynamicSharedMemorySize, SMEMSZ);

    k_softmax<<<(BB * NN * 32 + 255) / 256, 256>>>(cls);
    k_mid<<<BB, 1024>>>();
    k_nms_out<<<BB, 1024, SMEMSZ>>>(reg, props, hw, out);
}

// round 7
// speedup vs baseline: 2.6836x; 1.1764x over previous
#include <cuda_runtime.h>
#include <stdint.h>

#define BB 4
#define NN 2000
#define CC 80
#define NCLS 81
#define KPRE 2000
#define MAXOUT 100
#define CAP 8192
#define NHIST 5120
#define HBASE 0x1EA66
#define SCORE_THR 0.05f
#define IOU_THR 0.5f
#define MAX_RATIO 4.135166556742356f

// ---------------- scratch (device globals; self-cleaning, no allocation) -------
__device__ int g_cnt[BB];          // zeroed by k_main after read
__device__ int g_hist[BB][NHIST];  // zeroed by k_main after read
__device__ unsigned long long g_keys[BB][CAP];  // only [0,cnt) ever read

__device__ __forceinline__ int bucket_of(unsigned bits) {
    int b = (int)(bits >> 13) - HBASE;
    return min(NHIST - 1, max(0, b));
}

// -------- softmax (2 rows/warp for ILP) + threshold + compact + histogram ------
__global__ void k_softmax(const float* __restrict__ cls) {
    int gw = (blockIdx.x * blockDim.x + threadIdx.x) >> 5;
    int lane = threadIdx.x & 31;
    if (gw >= BB * NN / 2) return;
    int pr0 = gw * 2;                 // rows pr0, pr0+1 (same image: NN even)
    int img = pr0 / NN;
    const float* rowA = cls + (size_t)pr0 * NCLS;
    const float* rowB = rowA + NCLS;

    float a0 = rowA[lane], a1 = rowA[lane + 32];
    float a2 = (lane < NCLS - 64) ? rowA[lane + 64] : -1e30f;
    float b0 = rowB[lane], b1 = rowB[lane + 32];
    float b2 = (lane < NCLS - 64) ? rowB[lane + 64] : -1e30f;

    float mA = fmaxf(fmaxf(a0, a1), a2);
    float mB = fmaxf(fmaxf(b0, b1), b2);
    #pragma unroll
    for (int o = 16; o; o >>= 1) {
        mA = fmaxf(mA, __shfl_xor_sync(0xffffffffu, mA, o));
        mB = fmaxf(mB, __shfl_xor_sync(0xffffffffu, mB, o));
    }

    float eA0 = expf(a0 - mA), eA1 = expf(a1 - mA);
    float eA2 = (lane < NCLS - 64) ? expf(a2 - mA) : 0.0f;
    float eB0 = expf(b0 - mB), eB1 = expf(b1 - mB);
    float eB2 = (lane < NCLS - 64) ? expf(b2 - mB) : 0.0f;
    float sA = eA0 + eA1 + eA2;
    float sB = eB0 + eB1 + eB2;
    #pragma unroll
    for (int o = 16; o; o >>= 1) {
        sA += __shfl_xor_sync(0xffffffffu, sA, o);
        sB += __shfl_xor_sync(0xffffffffu, sB, o);
    }

    float sc[6];
    sc[0] = __fdiv_rn(eA0, sA); sc[1] = __fdiv_rn(eA1, sA); sc[2] = __fdiv_rn(eA2, sA);
    sc[3] = __fdiv_rn(eB0, sB); sc[4] = __fdiv_rn(eB1, sB); sc[5] = __fdiv_rn(eB2, sB);
    unsigned bal[6];
    int pc[6];
    int tot = 0;
    #pragma unroll
    for (int g = 0; g < 6; g++) {
        int grp = g % 3;
        bool pr = (grp < 2) ? (sc[g] > SCORE_THR)
                            : ((lane < CC - 64) && sc[g] > SCORE_THR);
        bal[g] = __ballot_sync(0xffffffffu, pr);
        pc[g] = __popc(bal[g]);
        tot += pc[g];
    }
    int base = 0;
    if (lane == 0 && tot) base = atomicAdd(&g_cnt[img], tot);
    base = __shfl_sync(0xffffffffu, base, 0);
    unsigned lm = (1u << lane) - 1u;

    #pragma unroll
    for (int g = 0; g < 6; g++) {
        if (bal[g] & (1u << lane)) {
            int grp = g % 3;
            int p = pr0 + (g / 3) - img * NN;   // local proposal idx
            int c = lane + grp * 32;
            int rank = __popc(bal[g] & lm);
            #pragma unroll
            for (int gg = 0; gg < 6; gg++) if (gg < g) rank += pc[gg];
            int pos = base + rank;
            if (pos < CAP) {
                unsigned flat = (unsigned)(p * CC + c);
                unsigned sb = __float_as_uint(sc[g]);
                g_keys[img][pos] =
                    ((unsigned long long)sb << 32) | (unsigned long long)(~flat);
                atomicAdd(&g_hist[img][bucket_of(sb)], 1);
            }
        }
    }
}

// -------- mega kernel: scan+scatter+segsort+decode+class-NMS+emit (1 blk/img) --
// dynamic smem layout (phase-aliased):
#define SM_OFF   0        /* int[5120]  (phases 1-3)  -> aliased by s_ob after  */
#define SM_BC    20480    /* int[5120]  (phases 1-3)  -> aliased by s_ob/s_ar   */
#define SM_SK    40960    /* u64[2048]  sorted keys (persists to emit)          */
#define SM_OB    0        /* float4[2048] offset boxes (phase 4+)               */
#define SM_AR    32768    /* float[2048]  offset areas (phase 4+)               */
#define SM_OUT   57344    /* float4[2048] output boxes                          */
#define SM_LAB   90112    /* u16[2048]                                          */
#define SM_ORD   94208    /* u16[2048]                                          */
#define SM_CCNT  98304    /* int[32*80]                                         */
#define SM_TOT   108544   /* int[80]                                            */
#define SM_START 108864   /* int[80]                                            */
#define SM_KEPT  109184   /* u32[64]                                            */
#define SM_WPRE  109440   /* int[64]                                            */
#define SM_KCNT  109696   /* int                                                */
#define SM_WTOT  109700   /* int[32]                                            */
#define SMEMSZ   109952

#define SCAN_U (NHIST / 1024)   /* 5 */

__global__ void k_main(const float* __restrict__ reg,
                       const float* __restrict__ props,
                       const int* __restrict__ hw,
                       float* __restrict__ out) {
    extern __shared__ unsigned char dyn[];
    int*      s_off  = (int*)(dyn + SM_OFF);
    int*      s_bc   = (int*)(dyn + SM_BC);
    unsigned long long* s_sk = (unsigned long long*)(dyn + SM_SK);
    float4*   s_ob   = (float4*)(dyn + SM_OB);
    float*    s_ar   = (float*)(dyn + SM_AR);
    float4*   s_out  = (float4*)(dyn + SM_OUT);
    unsigned short* s_lab = (unsigned short*)(dyn + SM_LAB);
    unsigned short* s_ord = (unsigned short*)(dyn + SM_ORD);
    int*      s_ccnt = (int*)(dyn + SM_CCNT);
    int*      s_tot  = (int*)(dyn + SM_TOT);
    int*      s_start= (int*)(dyn + SM_START);
    unsigned* s_kept = (unsigned*)(dyn + SM_KEPT);
    int*      s_wpre = (int*)(dyn + SM_WPRE);
    int*      s_kcnt = (int*)(dyn + SM_KCNT);
    int*      s_wtot = (int*)(dyn + SM_WTOT);

    int img = blockIdx.x, t = threadIdx.x;  // 1024
    int lane = t & 31, wid = t >> 5;
    unsigned lmlt = (1u << lane) - 1u;

    // ---- phase 1: histogram read+zero, suffix scan -> bucket offsets ----
    int cnt[SCAN_U];
    int tsum = 0;
    #pragma unroll
    for (int u = 0; u < SCAN_U; u++) {
        int b = NHIST - 1 - (t * SCAN_U + u);
        cnt[u] = g_hist[img][b];
        g_hist[img][b] = 0;
        s_bc[b] = 0;
        tsum += cnt[u];
    }
    int ws = tsum;
    #pragma unroll
    for (int o = 1; o < 32; o <<= 1) {
        int v = __shfl_up_sync(0xffffffffu, ws, o);
        if (lane >= o) ws += v;
    }
    if (lane == 31) s_wtot[wid] = ws;
    __syncthreads();
    if (wid == 0) {
        int v = s_wtot[lane];
        int sv = v;
        #pragma unroll
        for (int o = 1; o < 32; o <<= 1) {
            int x = __shfl_up_sync(0xffffffffu, sv, o);
            if (lane >= o) sv += x;
        }
        s_wtot[lane] = sv - v;
    }
    __syncthreads();
    int base = s_wtot[wid] + (ws - tsum);
    #pragma unroll
    for (int u = 0; u < SCAN_U; u++) {
        int b = NHIST - 1 - (t * SCAN_U + u);
        s_off[b] = base;
        base += cnt[u];
    }
    int total = min(g_cnt[img], CAP);
    if (t == 0) g_cnt[img] = 0;
    // zero key slots [.. 2048) not covered (tail) — all slots first:
    s_sk[t] = 0ULL; s_sk[t + 1024] = 0ULL;
    __syncthreads();

    // ---- phase 2: scatter keys into bucket-ordered smem slots ----
    for (int e = t; e < total; e += 1024) {
        unsigned long long key = g_keys[img][e];
        int b = bucket_of((unsigned)(key >> 32));
        int o = s_off[b];
        if (o < 2048) {
            int pos = o + atomicAdd(&s_bc[b], 1);
            if (pos < 2048) s_sk[pos] = key;
        }
    }
    __syncthreads();

    // ---- phase 3: per-bucket insertion sort in smem (descending) ----
    #pragma unroll
    for (int u = 0; u < SCAN_U; u++) {
        int b = NHIST - 1 - (t * SCAN_U + u);
        int o = s_off[b];
        if (o < 2048) {
            int end = min(o + s_bc[b], 2048);
            for (int i = o + 1; i < end; i++) {
                unsigned long long v = s_sk[i];
                int j = i - 1;
                while (j >= o && s_sk[j] < v) { s_sk[j + 1] = s_sk[j]; j--; }
                s_sk[j + 1] = v;
            }
        }
    }
    __syncthreads();

    // ---- phase 4: decode (exact reference fp; s_ob/s_ar alias dead s_off/s_bc)
    for (int i = t; i < 32 * 80; i += 1024) s_ccnt[i] = 0;
    float h = (float)hw[img * 2 + 0];
    float w = (float)hw[img * 2 + 1];
    float maxhw1 = __fadd_rn(fmaxf(h, w), 1.0f);

    // stage keys to registers BEFORE overwriting aliased region
    unsigned long long keyreg[2];
    keyreg[0] = s_sk[t];
    keyreg[1] = s_sk[t + 1024];
    __syncthreads();

    #pragma unroll
    for (int it = 0; it < 2; it++) {
        int r = t + it * 1024;
        unsigned long long key = keyreg[it];
        float sc = __uint_as_float((unsigned)(key >> 32));
        bool valid = (r < KPRE) && (sc > SCORE_THR);
        float4 ob = make_float4(0, 0, 0, 0), bx = make_float4(0, 0, 0, 0);
        float ar = 0.0f;
        int c = 0;
        if (valid) {
            int flat = (int)(~(unsigned)key);
            int p = flat / CC; c = flat % CC;
            const float* pb = props + ((size_t)img * NN + p) * 4;
            const float* dd = reg + (((size_t)img * NN + p) * CC + c) * 4;

            float dx = __fmul_rn(dd[0], 0.1f);
            float dy = __fmul_rn(dd[1], 0.1f);
            float dw = fminf(fmaxf(__fmul_rn(dd[2], 0.2f), -MAX_RATIO), MAX_RATIO);
            float dh = fminf(fmaxf(__fmul_rn(dd[3], 0.2f), -MAX_RATIO), MAX_RATIO);

            float px = __fmul_rn(__fadd_rn(pb[0], pb[2]), 0.5f);
            float py = __fmul_rn(__fadd_rn(pb[1], pb[3]), 0.5f);
            float pw = __fsub_rn(pb[2], pb[0]);
            float ph = __fsub_rn(pb[3], pb[1]);

            float gx = __fadd_rn(px, __fmul_rn(pw, dx));
            float gy = __fadd_rn(py, __fmul_rn(ph, dy));
            float gw = __fmul_rn(pw, expf(dw));
            float gh = __fmul_rn(ph, expf(dh));
            float hx = __fmul_rn(gw, 0.5f);
            float hy = __fmul_rn(gh, 0.5f);

            float x1 = fminf(fmaxf(__fsub_rn(gx, hx), 0.0f), w);
            float y1 = fminf(fmaxf(__fsub_rn(gy, hy), 0.0f), h);
            float x2 = fminf(fmaxf(__fadd_rn(gx, hx), 0.0f), w);
            float y2 = fminf(fmaxf(__fadd_rn(gy, hy), 0.0f), h);

            bx = make_float4(x1, y1, x2, y2);
            float off = __fmul_rn((float)c, maxhw1);
            ob = make_float4(__fadd_rn(x1, off), __fadd_rn(y1, off),
                             __fadd_rn(x2, off), __fadd_rn(y2, off));
            ar = __fmul_rn(__fsub_rn(ob.z, ob.x), __fsub_rn(ob.w, ob.y));
        }
        s_ob[r] = ob;
        s_out[r] = bx;
        s_ar[r] = ar;
        s_lab[r] = valid ? (unsigned short)c : (unsigned short)0xFFFF;
        unsigned bal = __ballot_sync(0xffffffffu, valid);
        if (lane == 0) s_kept[r >> 5] = bal;
    }
    __syncthreads();

    // ---- phase 5a: per-warp-chunk class counts ----
    #pragma unroll
    for (int half = 0; half < 2; half++) {
        int r = wid * 64 + half * 32 + lane;
        int lab = s_lab[r];
        if (lab != 0xFFFF) atomicAdd(&s_ccnt[wid * 80 + lab], 1);
    }
    __syncthreads();

    // ---- phase 5b: chunk-exclusive offsets + class totals + class starts ----
    if (t < 80) {
        int acc = 0;
        for (int w2 = 0; w2 < 32; w2++) {
            int v = s_ccnt[w2 * 80 + t];
            s_ccnt[w2 * 80 + t] = acc;
            acc += v;
        }
        s_tot[t] = acc;
    }
    __syncthreads();
    if (t == 0) {
        int a = 0;
        for (int c2 = 0; c2 < 80; c2++) { s_start[c2] = a; a += s_tot[c2]; }
    }
    __syncthreads();

    // ---- phase 5c: stable scatter into class groups ----
    #pragma unroll
    for (int half = 0; half < 2; half++) {
        int r = wid * 64 + half * 32 + lane;
        int lab = s_lab[r];
        bool valid = lab != 0xFFFF;
        unsigned key = valid ? (unsigned)lab : (0x100u + lane);
        unsigned mk = __match_any_sync(0xffffffffu, key);
        if (valid) {
            int rank = __popc(mk & lmlt);
            int pos = s_start[lab] + s_ccnt[wid * 80 + lab] + rank;
            s_ord[pos] = (unsigned short)r;
        }
        __syncwarp();
        if (valid && (mk & lmlt) == 0u) s_ccnt[wid * 80 + lab] += __popc(mk);
        __syncwarp();
    }
    __syncthreads();

    // ---- phase 6: per-class greedy NMS (warp per class) ----
    for (int c2 = wid; c2 < 80; c2 += 32) {
        int st = s_start[c2], en = st + s_tot[c2];
        for (int i = st; i < en - 1; i++) {
            int ri = s_ord[i];
            unsigned aw = s_kept[ri >> 5];
            if (aw & (1u << (ri & 31))) {
                float4 bi = s_ob[ri];
                float ai = s_ar[ri];
                for (int j = i + 1 + lane; j < en; j += 32) {
                    int rj = s_ord[j];
                    if (s_kept[rj >> 5] & (1u << (rj & 31))) {
                        float4 bj = s_ob[rj];
                        float ltx = fmaxf(bi.x, bj.x), lty = fmaxf(bi.y, bj.y);
                        float rbx = fminf(bi.z, bj.z), rby = fminf(bi.w, bj.w);
                        float wx = fmaxf(__fsub_rn(rbx, ltx), 0.0f);
                        float wy = fmaxf(__fsub_rn(rby, lty), 0.0f);
                        float inter = __fmul_rn(wx, wy);
                        float den = __fadd_rn(
                            __fsub_rn(__fadd_rn(ai, s_ar[rj]), inter), 1e-6f);
                        if (__fdiv_rn(inter, den) > IOU_THR)
                            atomicAnd(&s_kept[rj >> 5], ~(1u << (rj & 31)));
                    }
                }
            }
            __syncwarp();
        }
    }
    __syncthreads();

    // ---- phase 7: kept-bitmap exclusive prefix popcount ----
    if (wid == 0) {
        int v0 = __popc(s_kept[lane]);
        int v1 = __popc(s_kept[32 + lane]);
        int s0 = v0, s1 = v1;
        #pragma unroll
        for (int o = 1; o < 32; o <<= 1) {
            int x = __shfl_up_sync(0xffffffffu, s0, o);
            if (lane >= o) s0 += x;
            int y = __shfl_up_sync(0xffffffffu, s1, o);
            if (lane >= o) s1 += y;
        }
        int t0 = __shfl_sync(0xffffffffu, s0, 31);
        s_wpre[lane] = s0 - v0;
        s_wpre[32 + lane] = t0 + s1 - v1;
        if (lane == 31) *s_kcnt = t0 + s1;
    }
    __syncthreads();

    // ---- phase 8: emit boxes[B,100,4] | scores[B,100] | labels[B,100] ----
    int kc = *s_kcnt;
    if (t < MAXOUT && t >= kc) {
        float* bo = out + (size_t)(img * MAXOUT + t) * 4;
        bo[0] = 0.0f; bo[1] = 0.0f; bo[2] = 0.0f; bo[3] = 0.0f;
        out[BB * MAXOUT * 4 + img * MAXOUT + t] = 0.0f;
        out[BB * MAXOUT * 5 + img * MAXOUT + t] = -1.0f;
    }
    #pragma unroll
    for (int it = 0; it < 2; it++) {
        int r = t + it * 1024;
        unsigned wrd = s_kept[r >> 5];
        if (wrd & (1u << (r & 31))) {
            int rank = s_wpre[r >> 5] + __popc(wrd & ((1u << (r & 31)) - 1u));
            if (rank < MAXOUT) {
                float4 bx = s_out[r];
                unsigned long long key = keyreg[it];
                float sc = __uint_as_float((unsigned)(key >> 32));
                float lb = (float)((int)(~(unsigned)key) % CC);
                float* bo = out + (size_t)(img * MAXOUT + rank) * 4;
                bo[0] = bx.x; bo[1] = bx.y; bo[2] = bx.z; bo[3] = bx.w;
                out[BB * MAXOUT * 4 + img * MAXOUT + rank] = sc;
                out[BB * MAXOUT * 5 + img * MAXOUT + rank] = lb;
            }
        }
    }
}

// ---------------- launch (2 kernels) -------------------------------------------
extern "C" void kernel_launch(void* const* d_in, const int* in_sizes, int n_in,
                              void* d_out, int out_size) {
    const float* cls = (const float*)d_in[0];
    const float* reg = (const float*)d_in[1];
    const float* props = (const float*)d_in[2];
    const int* hw = (const int*)d_in[3];
    float* out = (float*)d_out;

    cudaFuncSetAttribute(k_main, cudaFuncAttributeMaxDynamicSharedMemorySize, SMEMSZ);

    k_softmax<<<(BB * NN / 2 * 32 + 255) / 256, 256>>>(cls);
    k_main<<<BB, 1024, SMEMSZ>>>(reg, props, hw, out);
}

// round 8
// speedup vs baseline: 3.6199x; 1.3489x over previous
#include <cuda_runtime.h>
#include <stdint.h>

#define BB 4
#define NN 2000
#define CC 80
#define NCLS 81
#define KPRE 2000
#define MAXOUT 100
#define CAP 8192
#define NHIST 5120
#define HBASE 0x1EA66
#define SCORE_THR 0.05f
#define IOU_THR 0.5f
#define MAX_RATIO 4.135166556742356f

// ---------------- scratch (device globals; self-cleaning, no allocation) -------
__device__ int g_cnt[BB];            // zeroed by k_sortgroup after read
__device__ int g_hist[BB][NHIST];    // zeroed by k_sortgroup after read
__device__ unsigned long long g_keys[BB][CAP];    // only [0,cnt) read
__device__ unsigned long long g_skeys[BB][2048];  // fully rewritten each run
__device__ unsigned short g_ord[BB][2048];        // [st,st+tot) read only
__device__ int g_start[BB][CC];                   // fully rewritten
__device__ int g_tot[BB][CC];                     // fully rewritten
__device__ unsigned g_kept[BB][64];               // fully rewritten
__device__ float4 g_box[BB][2048];                // kept entries written then read
__device__ float4 g_ob[BB][2048];                 // slow path only
__device__ float  g_ar[BB][2048];                 // slow path only

__device__ __forceinline__ int bucket_of(unsigned bits) {
    int b = (int)(bits >> 13) - HBASE;
    return min(NHIST - 1, max(0, b));
}

// exact reference fp decode (no FMA contraction)
__device__ __forceinline__ void decode_one(
    unsigned long long key, int img,
    const float* __restrict__ reg, const float* __restrict__ props,
    float h, float w, float maxhw1,
    float4* bx, float4* ob, float* ar)
{
    int flat = (int)(~(unsigned)key);
    int p = flat / CC, c = flat % CC;
    const float* pb = props + ((size_t)img * NN + p) * 4;
    const float* dd = reg + (((size_t)img * NN + p) * CC + c) * 4;

    float dx = __fmul_rn(dd[0], 0.1f);
    float dy = __fmul_rn(dd[1], 0.1f);
    float dw = fminf(fmaxf(__fmul_rn(dd[2], 0.2f), -MAX_RATIO), MAX_RATIO);
    float dh = fminf(fmaxf(__fmul_rn(dd[3], 0.2f), -MAX_RATIO), MAX_RATIO);

    float px = __fmul_rn(__fadd_rn(pb[0], pb[2]), 0.5f);
    float py = __fmul_rn(__fadd_rn(pb[1], pb[3]), 0.5f);
    float pw = __fsub_rn(pb[2], pb[0]);
    float ph = __fsub_rn(pb[3], pb[1]);

    float gx = __fadd_rn(px, __fmul_rn(pw, dx));
    float gy = __fadd_rn(py, __fmul_rn(ph, dy));
    float gw = __fmul_rn(pw, expf(dw));
    float gh = __fmul_rn(ph, expf(dh));
    float hx = __fmul_rn(gw, 0.5f);
    float hy = __fmul_rn(gh, 0.5f);

    float x1 = fminf(fmaxf(__fsub_rn(gx, hx), 0.0f), w);
    float y1 = fminf(fmaxf(__fsub_rn(gy, hy), 0.0f), h);
    float x2 = fminf(fmaxf(__fadd_rn(gx, hx), 0.0f), w);
    float y2 = fminf(fmaxf(__fadd_rn(gy, hy), 0.0f), h);

    *bx = make_float4(x1, y1, x2, y2);
    float off = __fmul_rn((float)c, maxhw1);
    float4 o = make_float4(__fadd_rn(x1, off), __fadd_rn(y1, off),
                           __fadd_rn(x2, off), __fadd_rn(y2, off));
    *ob = o;
    *ar = __fmul_rn(__fsub_rn(o.z, o.x), __fsub_rn(o.w, o.y));
}

__device__ __forceinline__ bool iou_gt(float4 bi, float ai, float4 bj, float aj) {
    float ltx = fmaxf(bi.x, bj.x), lty = fmaxf(bi.y, bj.y);
    float rbx = fminf(bi.z, bj.z), rby = fminf(bi.w, bj.w);
    float wx = fmaxf(__fsub_rn(rbx, ltx), 0.0f);
    float wy = fmaxf(__fsub_rn(rby, lty), 0.0f);
    float inter = __fmul_rn(wx, wy);
    float den = __fadd_rn(__fsub_rn(__fadd_rn(ai, aj), inter), 1e-6f);
    return __fdiv_rn(inter, den) > IOU_THR;
}

// -------- softmax (2 rows/warp) + threshold + compact + histogram --------------
__global__ void k_softmax(const float* __restrict__ cls) {
    int gw = (blockIdx.x * blockDim.x + threadIdx.x) >> 5;
    int lane = threadIdx.x & 31;
    if (gw >= BB * NN / 2) return;
    int pr0 = gw * 2;
    int img = pr0 / NN;
    const float* rowA = cls + (size_t)pr0 * NCLS;
    const float* rowB = rowA + NCLS;

    float a0 = rowA[lane], a1 = rowA[lane + 32];
    float a2 = (lane < NCLS - 64) ? rowA[lane + 64] : -1e30f;
    float b0 = rowB[lane], b1 = rowB[lane + 32];
    float b2 = (lane < NCLS - 64) ? rowB[lane + 64] : -1e30f;

    float mA = fmaxf(fmaxf(a0, a1), a2);
    float mB = fmaxf(fmaxf(b0, b1), b2);
    #pragma unroll
    for (int o = 16; o; o >>= 1) {
        mA = fmaxf(mA, __shfl_xor_sync(0xffffffffu, mA, o));
        mB = fmaxf(mB, __shfl_xor_sync(0xffffffffu, mB, o));
    }
    float eA0 = expf(a0 - mA), eA1 = expf(a1 - mA);
    float eA2 = (lane < NCLS - 64) ? expf(a2 - mA) : 0.0f;
    float eB0 = expf(b0 - mB), eB1 = expf(b1 - mB);
    float eB2 = (lane < NCLS - 64) ? expf(b2 - mB) : 0.0f;
    float sA = eA0 + eA1 + eA2;
    float sB = eB0 + eB1 + eB2;
    #pragma unroll
    for (int o = 16; o; o >>= 1) {
        sA += __shfl_xor_sync(0xffffffffu, sA, o);
        sB += __shfl_xor_sync(0xffffffffu, sB, o);
    }
    float sc[6];
    sc[0] = __fdiv_rn(eA0, sA); sc[1] = __fdiv_rn(eA1, sA); sc[2] = __fdiv_rn(eA2, sA);
    sc[3] = __fdiv_rn(eB0, sB); sc[4] = __fdiv_rn(eB1, sB); sc[5] = __fdiv_rn(eB2, sB);
    unsigned bal[6];
    int pc[6];
    int tot = 0;
    #pragma unroll
    for (int g = 0; g < 6; g++) {
        int grp = g % 3;
        bool pr = (grp < 2) ? (sc[g] > SCORE_THR)
                            : ((lane < CC - 64) && sc[g] > SCORE_THR);
        bal[g] = __ballot_sync(0xffffffffu, pr);
        pc[g] = __popc(bal[g]);
        tot += pc[g];
    }
    int base = 0;
    if (lane == 0 && tot) base = atomicAdd(&g_cnt[img], tot);
    base = __shfl_sync(0xffffffffu, base, 0);
    unsigned lm = (1u << lane) - 1u;
    #pragma unroll
    for (int g = 0; g < 6; g++) {
        if (bal[g] & (1u << lane)) {
            int grp = g % 3;
            int p = pr0 + (g / 3) - img * NN;
            int c = lane + grp * 32;
            int rank = __popc(bal[g] & lm);
            #pragma unroll
            for (int gg = 0; gg < 6; gg++) if (gg < g) rank += pc[gg];
            int pos = base + rank;
            if (pos < CAP) {
                unsigned flat = (unsigned)(p * CC + c);
                unsigned sb = __float_as_uint(sc[g]);
                g_keys[img][pos] =
                    ((unsigned long long)sb << 32) | (unsigned long long)(~flat);
                atomicAdd(&g_hist[img][bucket_of(sb)], 1);
            }
        }
    }
}

// -------- sort + class grouping (1 block/img) ----------------------------------
#define SM_OFF   0        /* int[5120] */
#define SM_BC    20480    /* int[5120] */
#define SM_SK    40960    /* u64[2048] */
#define SM_LAB   57344    /* u16[2048] */
#define SM_ORD   61440    /* u16[2048] */
#define SM_CCNT  65536    /* int[32*80] */
#define SM_TOT   75776    /* int[80] */
#define SM_START 76096    /* int[80] */
#define SM_WTOT  76416    /* int[32] */
#define SMEMSZ   76544
#define SCAN_U (NHIST / 1024)   /* 5 */

__global__ void k_sortgroup() {
    extern __shared__ unsigned char dyn[];
    int* s_off = (int*)(dyn + SM_OFF);
    int* s_bc = (int*)(dyn + SM_BC);
    unsigned long long* s_sk = (unsigned long long*)(dyn + SM_SK);
    unsigned short* s_lab = (unsigned short*)(dyn + SM_LAB);
    unsigned short* s_ord = (unsigned short*)(dyn + SM_ORD);
    int* s_ccnt = (int*)(dyn + SM_CCNT);
    int* s_tot = (int*)(dyn + SM_TOT);
    int* s_start = (int*)(dyn + SM_START);
    int* s_wtot = (int*)(dyn + SM_WTOT);

    int img = blockIdx.x, t = threadIdx.x;  // 1024
    int lane = t & 31, wid = t >> 5;
    unsigned lmlt = (1u << lane) - 1u;

    // phase 1: histogram read+zero, suffix scan
    int cnt[SCAN_U];
    int tsum = 0;
    #pragma unroll
    for (int u = 0; u < SCAN_U; u++) {
        int b = NHIST - 1 - (t * SCAN_U + u);
        cnt[u] = g_hist[img][b];
        g_hist[img][b] = 0;
        s_bc[b] = 0;
        tsum += cnt[u];
    }
    int ws = tsum;
    #pragma unroll
    for (int o = 1; o < 32; o <<= 1) {
        int v = __shfl_up_sync(0xffffffffu, ws, o);
        if (lane >= o) ws += v;
    }
    if (lane == 31) s_wtot[wid] = ws;
    __syncthreads();
    if (wid == 0) {
        int v = s_wtot[lane];
        int sv = v;
        #pragma unroll
        for (int o = 1; o < 32; o <<= 1) {
            int x = __shfl_up_sync(0xffffffffu, sv, o);
            if (lane >= o) sv += x;
        }
        s_wtot[lane] = sv - v;
    }
    __syncthreads();
    int base = s_wtot[wid] + (ws - tsum);
    #pragma unroll
    for (int u = 0; u < SCAN_U; u++) {
        int b = NHIST - 1 - (t * SCAN_U + u);
        s_off[b] = base;
        base += cnt[u];
    }
    int total = min(g_cnt[img], CAP);
    if (t == 0) g_cnt[img] = 0;
    s_sk[t] = 0ULL; s_sk[t + 1024] = 0ULL;
    __syncthreads();

    // phase 2: scatter
    for (int e = t; e < total; e += 1024) {
        unsigned long long key = g_keys[img][e];
        int b = bucket_of((unsigned)(key >> 32));
        int o = s_off[b];
        if (o < 2048) {
            int pos = o + atomicAdd(&s_bc[b], 1);
            if (pos < 2048) s_sk[pos] = key;
        }
    }
    __syncthreads();

    // phase 3: per-bucket insertion sort
    #pragma unroll
    for (int u = 0; u < SCAN_U; u++) {
        int b = NHIST - 1 - (t * SCAN_U + u);
        int o = s_off[b];
        if (o < 2048) {
            int end = min(o + s_bc[b], 2048);
            for (int i = o + 1; i < end; i++) {
                unsigned long long v = s_sk[i];
                int j = i - 1;
                while (j >= o && s_sk[j] < v) { s_sk[j + 1] = s_sk[j]; j--; }
                s_sk[j + 1] = v;
            }
        }
    }
    __syncthreads();

    // phase 4: labels + validity bitmap + export keys
    for (int i = t; i < 32 * 80; i += 1024) s_ccnt[i] = 0;
    #pragma unroll
    for (int it = 0; it < 2; it++) {
        int r = t + it * 1024;
        unsigned long long key = s_sk[r];
        g_skeys[img][r] = key;
        float sc = __uint_as_float((unsigned)(key >> 32));
        bool valid = (r < KPRE) && (sc > SCORE_THR);
        int lab = valid ? ((int)(~(unsigned)key) % CC) : 0xFFFF;
        s_lab[r] = (unsigned short)lab;
        unsigned bal = __ballot_sync(0xffffffffu, valid);
        if (lane == 0) g_kept[img][r >> 5] = bal;
    }
    __syncthreads();

    // phase 5a: per-warp-chunk class counts
    #pragma unroll
    for (int half = 0; half < 2; half++) {
        int r = wid * 64 + half * 32 + lane;
        int lab = s_lab[r];
        if (lab != 0xFFFF) atomicAdd(&s_ccnt[wid * 80 + lab], 1);
    }
    __syncthreads();

    // phase 5b: chunk-exclusive offsets + class starts
    if (t < 80) {
        int acc = 0;
        for (int w2 = 0; w2 < 32; w2++) {
            int v = s_ccnt[w2 * 80 + t];
            s_ccnt[w2 * 80 + t] = acc;
            acc += v;
        }
        s_tot[t] = acc;
        g_tot[img][t] = acc;
    }
    __syncthreads();
    if (t == 0) {
        int a = 0;
        for (int c2 = 0; c2 < 80; c2++) { s_start[c2] = a; a += s_tot[c2]; }
    }
    __syncthreads();
    if (t < 80) g_start[img][t] = s_start[t];

    // phase 5c: stable scatter into class groups
    #pragma unroll
    for (int half = 0; half < 2; half++) {
        int r = wid * 64 + half * 32 + lane;
        int lab = s_lab[r];
        bool valid = lab != 0xFFFF;
        unsigned key = valid ? (unsigned)lab : (0x100u + lane);
        unsigned mk = __match_any_sync(0xffffffffu, key);
        if (valid) {
            int rank = __popc(mk & lmlt);
            int pos = s_start[lab] + s_ccnt[wid * 80 + lab] + rank;
            s_ord[pos] = (unsigned short)r;
        }
        __syncwarp();
        if (valid && (mk & lmlt) == 0u) s_ccnt[wid * 80 + lab] += __popc(mk);
        __syncwarp();
    }
    __syncthreads();
    g_ord[img][t] = s_ord[t];
    g_ord[img][t + 1024] = s_ord[t + 1024];
}

// -------- NMS: one warp per (img, class); decode in-warp; register chain -------
__global__ void k_nms(const float* __restrict__ reg,
                      const float* __restrict__ props,
                      const int* __restrict__ hw) {
    int img = blockIdx.x;
    int lane = threadIdx.x & 31, wid = threadIdx.x >> 5;
    int c = blockIdx.y * 8 + wid;
    int st = g_start[img][c], tot = g_tot[img][c];
    if (tot == 0) return;

    float h = (float)hw[img * 2 + 0];
    float w = (float)hw[img * 2 + 1];
    float maxhw1 = __fadd_rn(fmaxf(h, w), 1.0f);

    if (tot <= 256) {
        int nr = (tot + 31) >> 5;
        float4 bb[8];
        float aa[8];
        int idxs[8];
        unsigned kmask = 0;
        #pragma unroll
        for (int u = 0; u < 8; u++) {
            idxs[u] = -1;
            bb[u] = make_float4(0, 0, 0, 0);
            aa[u] = 0.0f;
            if (u < nr) {
                int pos = u * 32 + lane;
                if (pos < tot) {
                    int idx = g_ord[img][st + pos];
                    idxs[u] = idx;
                    unsigned long long key = g_skeys[img][idx];
                    float4 bx;
                    decode_one(key, img, reg, props, h, w, maxhw1,
                               &bx, &bb[u], &aa[u]);
                    g_box[img][idx] = bx;
                    kmask |= 1u << u;
                }
            }
        }
        // greedy chain: i ascending in score order
        #pragma unroll
        for (int u = 0; u < 8; u++) {
            if (u >= nr) break;
            int ilim = min(tot - u * 32, 32);
            for (int li = 0; li < ilim; li++) {
                unsigned am = __ballot_sync(0xffffffffu, (kmask >> u) & 1u);
                if (!((am >> li) & 1u)) continue;
                int i = u * 32 + li;
                float bix = __shfl_sync(0xffffffffu, bb[u].x, li);
                float biy = __shfl_sync(0xffffffffu, bb[u].y, li);
                float biz = __shfl_sync(0xffffffffu, bb[u].z, li);
                float biw = __shfl_sync(0xffffffffu, bb[u].w, li);
                float ai  = __shfl_sync(0xffffffffu, aa[u], li);
                float4 bi = make_float4(bix, biy, biz, biw);
                #pragma unroll
                for (int v = 0; v < 8; v++) {
                    if (v >= nr) break;
                    int pos = v * 32 + lane;
                    if (pos > i && ((kmask >> v) & 1u)) {
                        if (iou_gt(bi, ai, bb[v], aa[v]))
                            kmask &= ~(1u << v);
                    }
                }
            }
        }
        // publish suppressed bits
        #pragma unroll
        for (int u = 0; u < 8; u++) {
            if (u >= nr) break;
            int idx = idxs[u];
            if (idx >= 0 && !((kmask >> u) & 1u))
                atomicAnd(&g_kept[img][idx >> 5], ~(1u << (idx & 31)));
        }
    } else {
        // slow path (class > 256 candidates; effectively never hit)
        for (int pos = lane; pos < tot; pos += 32) {
            int idx = g_ord[img][st + pos];
            unsigned long long key = g_skeys[img][idx];
            float4 bx, ob;
            float ar;
            decode_one(key, img, reg, props, h, w, maxhw1, &bx, &ob, &ar);
            g_box[img][idx] = bx;
            g_ob[img][idx] = ob;
            g_ar[img][idx] = ar;
        }
        __syncwarp();
        __threadfence();
        for (int i = 0; i < tot - 1; i++) {
            int ri = g_ord[img][st + i];
            if (g_kept[img][ri >> 5] & (1u << (ri & 31))) {
                float4 bi = g_ob[img][ri];
                float ai = g_ar[img][ri];
                for (int j = i + 1 + lane; j < tot; j += 32) {
                    int rj = g_ord[img][st + j];
                    if (g_kept[img][rj >> 5] & (1u << (rj & 31))) {
                        if (iou_gt(bi, ai, g_ob[img][rj], g_ar[img][rj]))
                            atomicAnd(&g_kept[img][rj >> 5], ~(1u << (rj & 31)));
                    }
                }
            }
            __syncwarp();
            __threadfence();
        }
    }
}

// -------- emit: prefix popcount over kept bitmap + gather ----------------------
__global__ void k_emit(float* __restrict__ out) {
    __shared__ int s_wpre[64];
    __shared__ int s_kcnt;
    int img = blockIdx.x, t = threadIdx.x;  // 128
    int lane = t & 31, wid = t >> 5;

    if (wid == 0) {
        int v0 = __popc(g_kept[img][lane]);
        int v1 = __popc(g_kept[img][32 + lane]);
        int s0 = v0, s1 = v1;
        #pragma unroll
        for (int o = 1; o < 32; o <<= 1) {
            int x = __shfl_up_sync(0xffffffffu, s0, o);
            if (lane >= o) s0 += x;
            int y = __shfl_up_sync(0xffffffffu, s1, o);
            if (lane >= o) s1 += y;
        }
        int t0 = __shfl_sync(0xffffffffu, s0, 31);
        s_wpre[lane] = s0 - v0;
        s_wpre[32 + lane] = t0 + s1 - v1;
        if (lane == 31) s_kcnt = t0 + s1;
    }
    __syncthreads();

    int kc = s_kcnt;
    if (t < MAXOUT && t >= kc) {
        float* bo = out + (size_t)(img * MAXOUT + t) * 4;
        bo[0] = 0.0f; bo[1] = 0.0f; bo[2] = 0.0f; bo[3] = 0.0f;
        out[BB * MAXOUT * 4 + img * MAXOUT + t] = 0.0f;
        out[BB * MAXOUT * 5 + img * MAXOUT + t] = -1.0f;
    }
    for (int r = t; r < 2048; r += 128) {
        unsigned wrd = g_kept[img][r >> 5];
        if (wrd & (1u << (r & 31))) {
            int rank = s_wpre[r >> 5] + __popc(wrd & ((1u << (r & 31)) - 1u));
            if (rank < MAXOUT) {
                float4 bx = g_box[img][r];
                unsigned long long key = g_skeys[img][r];
                float sc = __uint_as_float((unsigned)(key >> 32));
                float lb = (float)((int)(~(unsigned)key) % CC);
                float* bo = out + (size_t)(img * MAXOUT + rank) * 4;
                bo[0] = bx.x; bo[1] = bx.y; bo[2] = bx.z; bo[3] = bx.w;
                out[BB * MAXOUT * 4 + img * MAXOUT + rank] = sc;
                out[BB * MAXOUT * 5 + img * MAXOUT + rank] = lb;
            }
        }
    }
}

// ---------------- launch (4 kernels) -------------------------------------------
extern "C" void kernel_launch(void* const* d_in, const int* in_sizes, int n_in,
                              void* d_out, int out_size) {
    const float* cls = (const float*)d_in[0];
    const float* reg = (const float*)d_in[1];
    const float* props = (const float*)d_in[2];
    const int* hw = (const int*)d_in[3];
    float* out = (float*)d_out;

    cudaFuncSetAttribute(k_sortgroup, cudaFuncAttributeMaxDynamicSharedMemorySize, SMEMSZ);

    k_softmax<<<(BB * NN / 2 * 32 + 255) / 256, 256>>>(cls);
    k_sortgroup<<<BB, 1024, SMEMSZ>>>();
    dim3 ng(BB, 10);
    k_nms<<<ng, 256>>>(reg, props, hw);
    k_emit<<<BB, 128>>>(out);
}